// round 11
// baseline (speedup 1.0000x reference)
#include <cuda_runtime.h>
#include <cuda_bf16.h>
#include <stdint.h>

#define RBOX   500000
#define KCLS   10
#define NSCAL  (RBOX * 11)
#define NV4    (NSCAL / 4)
#define TTOP   2048
#define SCORE_T 0.05f
#define NMS_T   0.5f
#define CLS_OFF 3001.0f
#define IMG_W   1920.0f
#define IMG_H   1080.0f

#define HBASE  125542u              // bits(0.05f) >> 13
#define HBINS  4506
#define CAP    6144
#define ECAP   4096

#define RMT    512                  // k_rowmax threads
#define RMC    4                    // chunks per block
#define RMROWS 512                  // rows per chunk
#define RMB    245                  // 245 * 2048 rows >= RBOX
#define NGRP   (RBOX / 32)          // 15625 row-groups (exact)
#define MLIST  1024                 // per-class list capacity

// ---------------- device scratch ----------------
__device__ unsigned int       g_hist[HBINS];
__device__ unsigned int       g_rowmax[RBOX];
__device__ unsigned int       g_grpmax[NGRP];
__device__ unsigned int       g_done;
__device__ unsigned int       g_edone;
__device__ unsigned int       g_cutbin;
__device__ unsigned int       g_cnt;
__device__ unsigned long long g_keys[CAP];
__device__ float              g_nbox[TTOP * 4];
__device__ float              g_obox[TTOP * 4];
__device__ float              g_oscore[TTOP];
__device__ unsigned char      g_cls[TTOP];
__device__ unsigned int       g_ecnt;
__device__ unsigned int       g_edges[ECAP];

// ======== kernel 1: row max + histogram + group max + fused scan (last block) ========
__global__ void __launch_bounds__(RMT) k_rowmax(const float* __restrict__ scores,
                                                const float* __restrict__ center) {
    __shared__ __align__(16) float4 srow4[RMROWS * 11 / 4];   // 22528 B
    __shared__ unsigned sh[HBINS];                            // 18024 B
    __shared__ unsigned s_last;
    __shared__ unsigned wsum[16];
    __shared__ unsigned wsuf[17];
    float* srow = (float*)srow4;
    int t = threadIdx.x;
    unsigned lane = (unsigned)t & 31u, wid = (unsigned)t >> 5;
    for (int i = t; i < HBINS; i += RMT) sh[i] = 0u;

    unsigned blockrow0 = blockIdx.x * (RMROWS * RMC);
    for (int ch = 0; ch < RMC; ch++) {
        unsigned row0 = blockrow0 + (unsigned)ch * RMROWS;
        __syncthreads();                       // srow reuse + first-iter hist-zero cover
        if (row0 < RBOX) {
            unsigned base = (row0 * 11u) / 4u; // row0 multiple of 512 -> exact
            #pragma unroll
            for (int i = 0; i < 3; i++) {      // 3*512 = 1536 >= 1408
                unsigned li = (unsigned)i * RMT + (unsigned)t;
                if (li < RMROWS * 11 / 4) {
                    unsigned gq = base + li;
                    float4 v = (gq < NV4) ? __ldg(&((const float4*)scores)[gq])
                                          : make_float4(0.f, 0.f, 0.f, 0.f);
                    srow4[li] = v;
                }
            }
        }
        __syncthreads();
        unsigned r = row0 + (unsigned)t;
        unsigned bits = 0u;
        if (r < RBOX) {
            float c = __ldg(&center[r]);
            const float* rp = srow + t * 11 + 1;
            float m = rp[0];
            #pragma unroll
            for (int k = 1; k < 10; k++) m = fmaxf(m, rp[k]);
            float fg = m * c;
            if (fg > SCORE_T) {
                bits = __float_as_uint(fg);
                unsigned bin = (bits >> 13) - HBASE;
                if (bin >= HBINS) bin = HBINS - 1;
                atomicAdd(&sh[bin], 1u);
            }
            g_rowmax[r] = bits;
        }
        unsigned gmax = bits;                  // 32-row group max
        #pragma unroll
        for (int off = 16; off > 0; off >>= 1)
            gmax = max(gmax, __shfl_xor_sync(0xFFFFFFFFu, gmax, off));
        unsigned grp0 = row0 + (wid << 5);
        if (lane == 0u && grp0 < RBOX) g_grpmax[grp0 >> 5] = gmax;
    }
    __syncthreads();
    for (int i = t; i < HBINS; i += RMT) {
        unsigned v = sh[i];
        if (v) atomicAdd(&g_hist[i], v);
    }
    // -------- last-block-done -> suffix scan for theta_r --------
    __threadfence();
    __syncthreads();
    if (t == 0) s_last = (atomicAdd(&g_done, 1u) == RMB - 1u) ? 1u : 0u;
    __syncthreads();
    if (!s_last) return;

    const int CH = 9;                          // 512*9 = 4608 >= HBINS
    int lo = t * CH;
    unsigned loc[CH];
    unsigned p = 0u;
    #pragma unroll
    for (int k = 0; k < CH; k++) {
        int bin = lo + k;
        unsigned v = (bin < HBINS) ? __ldcg(&g_hist[bin]) : 0u;
        loc[k] = v; p += v;
    }
    unsigned s = p;                            // warp suffix scan
    #pragma unroll
    for (int off = 1; off < 32; off <<= 1) {
        unsigned v = __shfl_down_sync(0xFFFFFFFFu, s, off);
        if (lane + off < 32) s += v;
    }
    if (lane == 0u) wsum[wid] = s;
    __syncthreads();
    if (wid == 0u) {
        unsigned ws = (lane < 16u) ? wsum[lane] : 0u;
        #pragma unroll
        for (int off = 1; off < 32; off <<= 1) {
            unsigned v = __shfl_down_sync(0xFFFFFFFFu, ws, off);
            if (lane + off < 32) ws += v;
        }
        if (lane < 16u) wsuf[lane] = ws;
    }
    __syncthreads();
    unsigned sincl = s + ((wid < 15u) ? wsuf[wid + 1] : 0u);
    unsigned total = wsuf[0];
    if (total >= TTOP) {
        unsigned above = sincl - p;
        if (above < TTOP && sincl >= TTOP) {   // unique crossing thread
            unsigned run = above;
            for (int k = CH - 1; k >= 0; k--) {
                run += loc[k];
                if (run >= TTOP) { g_cutbin = (unsigned)(lo + k); break; }
            }
        }
    } else if (t == 0) {
        g_cutbin = 0u;
    }
    for (int bin = t; bin < HBINS; bin += RMT) g_hist[bin] = 0u;
    if (t == 0) { g_cnt = 0u; g_ecnt = 0u; g_done = 0u; }
}

// ======== kernel 2: collect candidate keys (warp per 32-row group, skip) ========
__global__ void __launch_bounds__(256) k_collect(const float* __restrict__ scores,
                                                 const float* __restrict__ center) {
    unsigned grp = (blockIdx.x * 256u + threadIdx.x) >> 5;
    unsigned lane = threadIdx.x & 31u;
    if (grp >= NGRP) return;
    unsigned cutb = HBASE + g_cutbin;                 // theta_r bin
    unsigned gmax = __ldg(&g_grpmax[grp]);
    if ((gmax >> 13) < cutb) return;                  // most groups skip here
    unsigned r = grp * 32u + lane;                    // r < RBOX (NGRP*32 == RBOX)
    unsigned bits = __ldg(&g_rowmax[r]);
    if ((bits >> 13) < cutb) return;
    float c = __ldg(&center[r]);
    const float* rp = scores + r * 11u + 1u;
    #pragma unroll
    for (int k = 0; k < 10; k++) {
        float fg = __ldg(&rp[k]) * c;
        if (fg > SCORE_T) {
            unsigned cb = __float_as_uint(fg);
            if ((cb >> 13) >= cutb) {
                unsigned j = r * 10u + (unsigned)k;
                unsigned pos = atomicAdd(&g_cnt, 1u);
                if (pos < CAP) {
                    g_keys[pos] = ((unsigned long long)cb << 32) |
                                  (unsigned long long)(0xFFFFFFFFu - j);
                }
            }
        }
    }
}

// ======== kernel 3: rank-by-count (L1-resident keys, warp per candidate) ========
__global__ void __launch_bounds__(1024) k_rank(const float* __restrict__ boxes) {
    unsigned n = g_cnt; if (n > CAP) n = CAP;
    unsigned cand = (blockIdx.x * 1024u + threadIdx.x) >> 5;
    unsigned lane = threadIdx.x & 31u;
    if (cand >= n) return;
    unsigned long long mykey = __ldg(&g_keys[cand]);
    unsigned cnt = 0u;
    for (unsigned j = lane; j < n; j += 32u)
        cnt += (__ldg(&g_keys[j]) > mykey) ? 1u : 0u;
    #pragma unroll
    for (int off = 16; off > 0; off >>= 1)
        cnt += __shfl_xor_sync(0xFFFFFFFFu, cnt, off);
    if (lane == 0u && cnt < TTOP) {
        unsigned rank = cnt;
        unsigned j = 0xFFFFFFFFu - (unsigned)(mykey & 0xFFFFFFFFull);
        float s = __uint_as_float((unsigned)(mykey >> 32));
        unsigned r = j / 10u;
        unsigned cls = j - r * 10u;
        float x1 = boxes[r * 4 + 0], y1 = boxes[r * 4 + 1];
        float x2 = boxes[r * 4 + 2], y2 = boxes[r * 4 + 3];
        float b0 = fminf(fmaxf(x1, 0.f), IMG_W);
        float b1 = fminf(fmaxf(y1, 0.f), IMG_H);
        float b2 = fminf(fmaxf(x2, 0.f), IMG_W);
        float b3 = fminf(fmaxf(y2, 0.f), IMG_H);
        float off2 = (float)cls * CLS_OFF;
        g_obox[rank * 4 + 0] = b0; g_obox[rank * 4 + 1] = b1;
        g_obox[rank * 4 + 2] = b2; g_obox[rank * 4 + 3] = b3;
        g_nbox[rank * 4 + 0] = b0 + off2; g_nbox[rank * 4 + 1] = b1 + off2;
        g_nbox[rank * 4 + 2] = b2 + off2; g_nbox[rank * 4 + 3] = b3 + off2;
        g_oscore[rank] = s;
        g_cls[rank] = (unsigned char)cls;
    }
}

// ======== kernel 4: per-class IoU edges + fused Jacobi NMS + output ========
// Cross-class pairs can never overlap (offset 3001 > image extent), so all
// suppression edges are within-class: 10 blocks, one class each.
__global__ void __launch_bounds__(256) k_edges(float* __restrict__ out) {
    __shared__ float sx1[MLIST], sy1[MLIST], sx2[MLIST], sy2[MLIST];  // 16 KB
    __shared__ unsigned short sridx[MLIST];                           // 2 KB
    __shared__ unsigned s_m;
    int t = threadIdx.x;
    int c = blockIdx.x;
    if (t == 0) s_m = 0u;
    __syncthreads();
    // compact this class's boxes (rank order within list irrelevant)
    for (int i = t; i < TTOP; i += 256) {
        if ((int)g_cls[i] == c) {
            unsigned p = atomicAdd(&s_m, 1u);
            if (p < MLIST) {
                sridx[p] = (unsigned short)i;
                sx1[p] = g_nbox[i * 4 + 0];
                sy1[p] = g_nbox[i * 4 + 1];
                sx2[p] = g_nbox[i * 4 + 2];
                sy2[p] = g_nbox[i * 4 + 3];
            }
        }
    }
    __syncthreads();
    unsigned m = s_m; if (m > MLIST) m = MLIST;
    for (unsigned p = t; p < m; p += 256) {
        float ax1 = sx1[p], ay1 = sy1[p], ax2 = sx2[p], ay2 = sy2[p];
        float aarea = fmaxf(ax2 - ax1, 0.f) * fmaxf(ay2 - ay1, 0.f);
        unsigned ri = sridx[p];
        for (unsigned q = p + 1; q < m; q++) {
            float w = fminf(ax2, sx2[q]) - fmaxf(ax1, sx1[q]);
            float h = fminf(ay2, sy2[q]) - fmaxf(ay1, sy1[q]);
            if (w > 0.f && h > 0.f) {
                float inter = w * h;
                float barea = fmaxf(sx2[q] - sx1[q], 0.f) * fmaxf(sy2[q] - sy1[q], 0.f);
                float denom = aarea + barea - inter + 1e-9f;
                if (inter > 0.45f * denom) {
                    float iou = inter / denom;          // exact IEEE div (rare)
                    if (iou > NMS_T) {
                        unsigned rj = sridx[q];
                        unsigned lo2 = min(ri, rj), hi2 = max(ri, rj);
                        unsigned pos = atomicAdd(&g_ecnt, 1u);
                        if (pos < ECAP) g_edges[pos] = (lo2 << 16) | hi2;
                    }
                }
            }
        }
    }
    // -------- last-block-done -> Jacobi fixpoint NMS + output --------
    __shared__ unsigned s_last;
    __threadfence();
    __syncthreads();
    if (t == 0) s_last = (atomicAdd(&g_edone, 1u) == KCLS - 1u) ? 1u : 0u;
    __syncthreads();
    if (!s_last) return;
    {
        __shared__ unsigned se[ECAP];                   // 16 KB
        __shared__ unsigned char valid[TTOP];
        __shared__ unsigned char ka[TTOP];
        __shared__ unsigned char kb[TTOP];
        __shared__ int s_changed;
        unsigned n = g_cnt; if (n > CAP) n = CAP;
        unsigned E = __ldcg(&g_ecnt); if (E > ECAP) E = ECAP;
        for (unsigned i = t; i < E; i += 256) se[i] = __ldcg(&g_edges[i]);
        for (unsigned i = t; i < TTOP; i += 256) {
            unsigned char v = (i < n && g_oscore[i] > SCORE_T) ? 1 : 0;
            valid[i] = v; ka[i] = v;
        }
        __syncthreads();
        for (int round = 0; round < TTOP; round++) {
            if (t == 0) s_changed = 0;
            for (unsigned i = t; i < TTOP; i += 256) kb[i] = valid[i];
            __syncthreads();
            for (unsigned e = t; e < E; e += 256) {
                unsigned v = se[e];
                unsigned i = v >> 16, j = v & 0xFFFFu;
                if (ka[i]) kb[j] = 0;
            }
            __syncthreads();
            int ch = 0;
            for (unsigned i = t; i < TTOP; i += 256) {
                if (kb[i] != ka[i]) ch = 1;
                ka[i] = kb[i];
            }
            if (ch) s_changed = 1;
            __syncthreads();
            if (!s_changed) break;
        }
        for (unsigned i = t; i < TTOP; i += 256) {
            bool kp = ka[i] != 0;
            out[i * 5 + 0] = kp ? g_obox[i * 4 + 0] : 0.f;
            out[i * 5 + 1] = kp ? g_obox[i * 4 + 1] : 0.f;
            out[i * 5 + 2] = kp ? g_obox[i * 4 + 2] : 0.f;
            out[i * 5 + 3] = kp ? g_obox[i * 4 + 3] : 0.f;
            out[i * 5 + 4] = kp ? g_oscore[i] : 0.f;
        }
        if (t == 0) g_edone = 0u;              // reset for next replay
    }
}

// ---------------- launch ----------------
extern "C" void kernel_launch(void* const* d_in, const int* in_sizes, int n_in,
                              void* d_out, int out_size) {
    const float* boxes  = nullptr;
    const float* scores = nullptr;
    const float* center = nullptr;
    for (int i = 0; i < n_in; i++) {
        if (in_sizes[i] == RBOX * 4)       boxes  = (const float*)d_in[i];
        else if (in_sizes[i] == RBOX * 11) scores = (const float*)d_in[i];
        else if (in_sizes[i] == RBOX)      center = (const float*)d_in[i];
    }
    if (!boxes)  boxes  = (const float*)d_in[0];
    if (!scores) scores = (const float*)d_in[1];
    if (!center) center = (const float*)d_in[2];
    float* out = (float*)d_out;

    k_rowmax<<<RMB, RMT>>>(scores, center);                    // + fused theta_r scan
    k_collect<<<(NGRP * 32 + 255) / 256, 256>>>(scores, center);
    k_rank<<<(CAP * 32 + 1023) / 1024, 1024>>>(boxes);
    k_edges<<<KCLS, 256>>>(out);                               // + fused NMS/output
}

// round 12
// speedup vs baseline: 1.5756x; 1.5756x over previous
#include <cuda_runtime.h>
#include <cuda_bf16.h>
#include <stdint.h>

#define RBOX   500000
#define KCLS   10
#define NSCAL  (RBOX * 11)
#define NV4    (NSCAL / 4)
#define TTOP   2048
#define SCORE_T 0.05f
#define NMS_T   0.5f
#define CLS_OFF 3001.0f
#define IMG_W   1920.0f
#define IMG_H   1080.0f

#define HBASE  125542u              // bits(0.05f) >> 13
#define HBINS  4506
#define CAP    6144
#define ECAP   4096

#define RMT    512                  // k_rowmax threads
#define RMC    4                    // chunks per block
#define RMROWS 512                  // rows per chunk
#define RMB    245                  // 245 * 2048 rows >= RBOX
#define NGRP   (RBOX / 32)          // 15625 row-groups (exact)
#define MLIST  1024                 // per-class list capacity

// ---------------- device scratch ----------------
__device__ unsigned int       g_hist[HBINS];
__device__ unsigned int       g_rowmax[RBOX];
__device__ unsigned int       g_grpmax[NGRP];
__device__ unsigned int       g_done;
__device__ unsigned int       g_edone;
__device__ unsigned int       g_cutbin;
__device__ unsigned int       g_cnt;
__device__ unsigned long long g_keys[CAP];
__device__ float              g_nbox[TTOP * 4];
__device__ float              g_obox[TTOP * 4];
__device__ float              g_oscore[TTOP];
__device__ unsigned char      g_cls[TTOP];
__device__ unsigned int       g_ecnt;
__device__ unsigned int       g_edges[ECAP];

// ======== kernel 1: row max + histogram + group max + fused scan (last block) ========
__global__ void __launch_bounds__(RMT) k_rowmax(const float* __restrict__ scores,
                                                const float* __restrict__ center) {
    __shared__ __align__(16) float4 srow4[RMROWS * 11 / 4];   // 22528 B
    __shared__ unsigned sh[HBINS];                            // 18024 B
    __shared__ unsigned s_last;
    __shared__ unsigned wsum[16];
    __shared__ unsigned wsuf[17];
    float* srow = (float*)srow4;
    int t = threadIdx.x;
    unsigned lane = (unsigned)t & 31u, wid = (unsigned)t >> 5;
    for (int i = t; i < HBINS; i += RMT) sh[i] = 0u;

    unsigned blockrow0 = blockIdx.x * (RMROWS * RMC);
    for (int ch = 0; ch < RMC; ch++) {
        unsigned row0 = blockrow0 + (unsigned)ch * RMROWS;
        __syncthreads();                       // srow reuse + first-iter hist-zero cover
        if (row0 < RBOX) {
            unsigned base = (row0 * 11u) / 4u; // row0 multiple of 512 -> exact
            #pragma unroll
            for (int i = 0; i < 3; i++) {      // 3*512 = 1536 >= 1408
                unsigned li = (unsigned)i * RMT + (unsigned)t;
                if (li < RMROWS * 11 / 4) {
                    unsigned gq = base + li;
                    float4 v = (gq < NV4) ? __ldg(&((const float4*)scores)[gq])
                                          : make_float4(0.f, 0.f, 0.f, 0.f);
                    srow4[li] = v;
                }
            }
        }
        __syncthreads();
        unsigned r = row0 + (unsigned)t;
        unsigned bits = 0u;
        if (r < RBOX) {
            float c = __ldg(&center[r]);
            const float* rp = srow + t * 11 + 1;
            float m = rp[0];
            #pragma unroll
            for (int k = 1; k < 10; k++) m = fmaxf(m, rp[k]);
            float fg = m * c;
            if (fg > SCORE_T) {
                bits = __float_as_uint(fg);
                unsigned bin = (bits >> 13) - HBASE;
                if (bin >= HBINS) bin = HBINS - 1;
                atomicAdd(&sh[bin], 1u);
            }
            g_rowmax[r] = bits;
        }
        unsigned gmax = bits;                  // 32-row group max
        #pragma unroll
        for (int off = 16; off > 0; off >>= 1)
            gmax = max(gmax, __shfl_xor_sync(0xFFFFFFFFu, gmax, off));
        unsigned grp0 = row0 + (wid << 5);
        if (lane == 0u && grp0 < RBOX) g_grpmax[grp0 >> 5] = gmax;
    }
    __syncthreads();
    for (int i = t; i < HBINS; i += RMT) {
        unsigned v = sh[i];
        if (v) atomicAdd(&g_hist[i], v);
    }
    // -------- last-block-done -> suffix scan for theta_r --------
    __threadfence();
    __syncthreads();
    if (t == 0) s_last = (atomicAdd(&g_done, 1u) == RMB - 1u) ? 1u : 0u;
    __syncthreads();
    if (!s_last) return;

    const int CH = 9;                          // 512*9 = 4608 >= HBINS
    int lo = t * CH;
    unsigned loc[CH];
    unsigned p = 0u;
    #pragma unroll
    for (int k = 0; k < CH; k++) {
        int bin = lo + k;
        unsigned v = (bin < HBINS) ? __ldcg(&g_hist[bin]) : 0u;
        loc[k] = v; p += v;
    }
    unsigned s = p;                            // warp suffix scan
    #pragma unroll
    for (int off = 1; off < 32; off <<= 1) {
        unsigned v = __shfl_down_sync(0xFFFFFFFFu, s, off);
        if (lane + off < 32) s += v;
    }
    if (lane == 0u) wsum[wid] = s;
    __syncthreads();
    if (wid == 0u) {
        unsigned ws = (lane < 16u) ? wsum[lane] : 0u;
        #pragma unroll
        for (int off = 1; off < 32; off <<= 1) {
            unsigned v = __shfl_down_sync(0xFFFFFFFFu, ws, off);
            if (lane + off < 32) ws += v;
        }
        if (lane < 16u) wsuf[lane] = ws;
    }
    __syncthreads();
    unsigned sincl = s + ((wid < 15u) ? wsuf[wid + 1] : 0u);
    unsigned total = wsuf[0];
    if (total >= TTOP) {
        unsigned above = sincl - p;
        if (above < TTOP && sincl >= TTOP) {   // unique crossing thread
            unsigned run = above;
            for (int k = CH - 1; k >= 0; k--) {
                run += loc[k];
                if (run >= TTOP) { g_cutbin = (unsigned)(lo + k); break; }
            }
        }
    } else if (t == 0) {
        g_cutbin = 0u;
    }
    for (int bin = t; bin < HBINS; bin += RMT) g_hist[bin] = 0u;
    if (t == 0) { g_cnt = 0u; g_ecnt = 0u; g_done = 0u; }
}

// ======== kernel 2: collect candidate keys (warp per 32-row group, skip) ========
__global__ void __launch_bounds__(256) k_collect(const float* __restrict__ scores,
                                                 const float* __restrict__ center) {
    unsigned grp = (blockIdx.x * 256u + threadIdx.x) >> 5;
    unsigned lane = threadIdx.x & 31u;
    if (grp >= NGRP) return;
    unsigned cutb = HBASE + g_cutbin;                 // theta_r bin
    unsigned gmax = __ldg(&g_grpmax[grp]);
    if ((gmax >> 13) < cutb) return;                  // most groups skip here
    unsigned r = grp * 32u + lane;                    // r < RBOX (NGRP*32 == RBOX)
    unsigned bits = __ldg(&g_rowmax[r]);
    if ((bits >> 13) < cutb) return;
    float c = __ldg(&center[r]);
    const float* rp = scores + r * 11u + 1u;
    #pragma unroll
    for (int k = 0; k < 10; k++) {
        float fg = __ldg(&rp[k]) * c;
        if (fg > SCORE_T) {
            unsigned cb = __float_as_uint(fg);
            if ((cb >> 13) >= cutb) {
                unsigned j = r * 10u + (unsigned)k;
                unsigned pos = atomicAdd(&g_cnt, 1u);
                if (pos < CAP) {
                    g_keys[pos] = ((unsigned long long)cb << 32) |
                                  (unsigned long long)(0xFFFFFFFFu - j);
                }
            }
        }
    }
}

// ======== kernel 3: rank-by-count (L1-resident keys, warp per candidate) ========
__global__ void __launch_bounds__(1024) k_rank(const float* __restrict__ boxes) {
    unsigned n = g_cnt; if (n > CAP) n = CAP;
    unsigned cand = (blockIdx.x * 1024u + threadIdx.x) >> 5;
    unsigned lane = threadIdx.x & 31u;
    if (cand >= n) return;
    unsigned long long mykey = __ldg(&g_keys[cand]);
    unsigned cnt = 0u;
    for (unsigned j = lane; j < n; j += 32u)
        cnt += (__ldg(&g_keys[j]) > mykey) ? 1u : 0u;
    #pragma unroll
    for (int off = 16; off > 0; off >>= 1)
        cnt += __shfl_xor_sync(0xFFFFFFFFu, cnt, off);
    if (lane == 0u && cnt < TTOP) {
        unsigned rank = cnt;
        unsigned j = 0xFFFFFFFFu - (unsigned)(mykey & 0xFFFFFFFFull);
        float s = __uint_as_float((unsigned)(mykey >> 32));
        unsigned r = j / 10u;
        unsigned cls = j - r * 10u;
        float x1 = boxes[r * 4 + 0], y1 = boxes[r * 4 + 1];
        float x2 = boxes[r * 4 + 2], y2 = boxes[r * 4 + 3];
        float b0 = fminf(fmaxf(x1, 0.f), IMG_W);
        float b1 = fminf(fmaxf(y1, 0.f), IMG_H);
        float b2 = fminf(fmaxf(x2, 0.f), IMG_W);
        float b3 = fminf(fmaxf(y2, 0.f), IMG_H);
        float off2 = (float)cls * CLS_OFF;
        g_obox[rank * 4 + 0] = b0; g_obox[rank * 4 + 1] = b1;
        g_obox[rank * 4 + 2] = b2; g_obox[rank * 4 + 3] = b3;
        g_nbox[rank * 4 + 0] = b0 + off2; g_nbox[rank * 4 + 1] = b1 + off2;
        g_nbox[rank * 4 + 2] = b2 + off2; g_nbox[rank * 4 + 3] = b3 + off2;
        g_oscore[rank] = s;
        g_cls[rank] = (unsigned char)cls;
    }
}

// ======== kernel 4: per-class IoU edges (32x32 pair tiling) + fused NMS + output ========
// Cross-class pairs never overlap (offset 3001 > image extent) -> edges are
// within-class only. 10 blocks x 1024 threads; warp w owns p in {w, w+32, ...}
// (uniform p per warp -> no divergence), lanes stride q (coalesced smem).
__global__ void __launch_bounds__(1024) k_edges(float* __restrict__ out) {
    __shared__ float sx1[MLIST], sy1[MLIST], sx2[MLIST], sy2[MLIST];  // 16 KB
    __shared__ unsigned short sridx[MLIST];                           // 2 KB
    __shared__ unsigned s_m;
    int t = threadIdx.x;
    int c = blockIdx.x;
    unsigned lane = (unsigned)t & 31u;     // q-lane
    unsigned wrp  = (unsigned)t >> 5;      // p-slot (32 warps)
    if (t == 0) s_m = 0u;
    __syncthreads();
    // compact this class's boxes (list order irrelevant)
    for (int i = t; i < TTOP; i += 1024) {
        if ((int)g_cls[i] == c) {
            unsigned p = atomicAdd(&s_m, 1u);
            if (p < MLIST) {
                sridx[p] = (unsigned short)i;
                sx1[p] = g_nbox[i * 4 + 0];
                sy1[p] = g_nbox[i * 4 + 1];
                sx2[p] = g_nbox[i * 4 + 2];
                sy2[p] = g_nbox[i * 4 + 3];
            }
        }
    }
    __syncthreads();
    unsigned m = s_m; if (m > MLIST) m = MLIST;
    for (unsigned p = wrp; p < m; p += 32u) {          // ~7 outer iterations
        float ax1 = sx1[p], ay1 = sy1[p], ax2 = sx2[p], ay2 = sy2[p];
        float aarea = fmaxf(ax2 - ax1, 0.f) * fmaxf(ay2 - ay1, 0.f);
        unsigned ri = sridx[p];
        for (unsigned q = p + 1u + lane; q < m; q += 32u) {  // <=7 inner iterations
            float w = fminf(ax2, sx2[q]) - fmaxf(ax1, sx1[q]);
            float h = fminf(ay2, sy2[q]) - fmaxf(ay1, sy1[q]);
            if (w > 0.f && h > 0.f) {
                float inter = w * h;
                float barea = fmaxf(sx2[q] - sx1[q], 0.f) * fmaxf(sy2[q] - sy1[q], 0.f);
                float denom = aarea + barea - inter + 1e-9f;
                if (inter > 0.45f * denom) {
                    float iou = inter / denom;          // exact IEEE div (rare)
                    if (iou > NMS_T) {
                        unsigned rj = sridx[q];
                        unsigned lo2 = min(ri, (unsigned)rj), hi2 = max(ri, (unsigned)rj);
                        unsigned pos = atomicAdd(&g_ecnt, 1u);
                        if (pos < ECAP) g_edges[pos] = (lo2 << 16) | hi2;
                    }
                }
            }
        }
    }
    // -------- last-block-done -> Jacobi fixpoint NMS + output --------
    __shared__ unsigned s_last;
    __threadfence();
    __syncthreads();
    if (t == 0) s_last = (atomicAdd(&g_edone, 1u) == KCLS - 1u) ? 1u : 0u;
    __syncthreads();
    if (!s_last) return;
    {
        __shared__ unsigned se[ECAP];                   // 16 KB
        __shared__ unsigned char valid[TTOP];
        __shared__ unsigned char ka[TTOP];
        __shared__ unsigned char kb[TTOP];
        __shared__ int s_changed;
        unsigned n = g_cnt; if (n > CAP) n = CAP;
        unsigned E = __ldcg(&g_ecnt); if (E > ECAP) E = ECAP;
        for (unsigned i = t; i < E; i += 1024) se[i] = __ldcg(&g_edges[i]);
        for (unsigned i = t; i < TTOP; i += 1024) {
            unsigned char v = (i < n && g_oscore[i] > SCORE_T) ? 1 : 0;
            valid[i] = v; ka[i] = v;
        }
        __syncthreads();
        for (int round = 0; round < TTOP; round++) {
            if (t == 0) s_changed = 0;
            for (unsigned i = t; i < TTOP; i += 1024) kb[i] = valid[i];
            __syncthreads();
            for (unsigned e = t; e < E; e += 1024) {
                unsigned v = se[e];
                unsigned i = v >> 16, j = v & 0xFFFFu;
                if (ka[i]) kb[j] = 0;
            }
            __syncthreads();
            int ch = 0;
            for (unsigned i = t; i < TTOP; i += 1024) {
                if (kb[i] != ka[i]) ch = 1;
                ka[i] = kb[i];
            }
            if (ch) s_changed = 1;
            __syncthreads();
            if (!s_changed) break;
        }
        for (unsigned i = t; i < TTOP; i += 1024) {
            bool kp = ka[i] != 0;
            out[i * 5 + 0] = kp ? g_obox[i * 4 + 0] : 0.f;
            out[i * 5 + 1] = kp ? g_obox[i * 4 + 1] : 0.f;
            out[i * 5 + 2] = kp ? g_obox[i * 4 + 2] : 0.f;
            out[i * 5 + 3] = kp ? g_obox[i * 4 + 3] : 0.f;
            out[i * 5 + 4] = kp ? g_oscore[i] : 0.f;
        }
        if (t == 0) g_edone = 0u;              // reset for next replay
    }
}

// ---------------- launch ----------------
extern "C" void kernel_launch(void* const* d_in, const int* in_sizes, int n_in,
                              void* d_out, int out_size) {
    const float* boxes  = nullptr;
    const float* scores = nullptr;
    const float* center = nullptr;
    for (int i = 0; i < n_in; i++) {
        if (in_sizes[i] == RBOX * 4)       boxes  = (const float*)d_in[i];
        else if (in_sizes[i] == RBOX * 11) scores = (const float*)d_in[i];
        else if (in_sizes[i] == RBOX)      center = (const float*)d_in[i];
    }
    if (!boxes)  boxes  = (const float*)d_in[0];
    if (!scores) scores = (const float*)d_in[1];
    if (!center) center = (const float*)d_in[2];
    float* out = (float*)d_out;

    k_rowmax<<<RMB, RMT>>>(scores, center);                    // + fused theta_r scan
    k_collect<<<(NGRP * 32 + 255) / 256, 256>>>(scores, center);
    k_rank<<<(CAP * 32 + 1023) / 1024, 1024>>>(boxes);
    k_edges<<<KCLS, 1024>>>(out);                              // + fused NMS/output
}